// round 9
// baseline (speedup 1.0000x reference)
#include <cuda_runtime.h>
#include <cstdint>

// ============================================================================
// LSTM cell, base sm_103 ISA. tf32 mma.sync m16n8k8, cp.async 4-slot TK=32,
// fragment-packed operands, register double-buffered fragments with
// cross-stage prefetch, SINGLE barrier per k-chunk (cutlass multistage order).
// CTA 256x128, 256 threads, warp tile 64x64. Fused gate epilogue.
//
// z[4096, 8192] = A[4096, 4096] @ B[4096, 8192]
//   A = [x | h], B[k][4u+g] = W{x,h}{f,i,o,g}[k][u]  (gate-interleaved)
// ============================================================================

#define MTOT 4096
#define KTOT 4096
#define NTOT 8192
#define UDIM 2048

#define TM 256
#define TN 128
#define TK 32          // 4 k8 sub-steps per stage
#define STAGES 4
#define NTHREADS 256

#define MBTOT 256              // MTOT/16
#define NBPTOT 512             // NTOT/16 (n-fragment pairs)

#define SA_STAGE 32768         // 4 k8 * 16 mb * 512 B
#define SB_STAGE 16384         // 4 k8 * 8 nbp * 512 B
#define STAGE_BYTES (SA_STAGE + SB_STAGE)      // 49152
#define PIPE_BYTES (STAGES * STAGE_BYTES)      // 196608
#define ZLD 132
#define SMEM_BYTES PIPE_BYTES

// Fragment-packed tf32 operands.
// g_Ap[k8][mb][lane][4] : lane=(gq<<2)|kq holds A[mb*16+gq+{0,8}][k8*8+kq+{0,4}]
// g_Bp[k8][nbp][lane][4]: lane=(nq<<2)|kq holds B[k8*8+kq+{0,4}][nbp*16+nq+{0,8}]
static __device__ __align__(16) float g_Ap[(size_t)MTOT * KTOT];   // 64 MB
static __device__ __align__(16) float g_Bp[(size_t)KTOT * NTOT];   // 128 MB

// ---------------------------------------------------------------- helpers
__device__ __forceinline__ uint32_t smem_u32(const void* p) {
    uint32_t a;
    asm("{ .reg .u64 t; cvta.to.shared.u64 t, %1; cvt.u32.u64 %0, t; }"
        : "=r"(a) : "l"(p));
    return a;
}

__device__ __forceinline__ uint32_t tf32r(float v) {   // round-to-nearest tf32
    uint32_t r;
    asm("cvt.rna.tf32.f32 %0, %1;" : "=r"(r) : "f"(v));
    return r;
}

__device__ __forceinline__ void cp16(uint32_t dst, const void* src) {
    asm volatile("cp.async.cg.shared.global [%0], [%1], 16;"
                 :: "r"(dst), "l"(src) : "memory");
}
__device__ __forceinline__ void cp_commit() {
    asm volatile("cp.async.commit_group;" ::: "memory");
}
template <int N>
__device__ __forceinline__ void cp_wait() {
    asm volatile("cp.async.wait_group %0;" :: "n"(N) : "memory");
}

__device__ __forceinline__ void mma8(float* d, const uint32_t* a, const uint32_t* b) {
    asm volatile(
        "mma.sync.aligned.m16n8k8.row.col.f32.tf32.tf32.f32 "
        "{%0,%1,%2,%3}, {%4,%5,%6,%7}, {%8,%9}, {%0,%1,%2,%3};"
        : "+f"(d[0]), "+f"(d[1]), "+f"(d[2]), "+f"(d[3])
        : "r"(a[0]), "r"(a[1]), "r"(a[2]), "r"(a[3]), "r"(b[0]), "r"(b[1]));
}

__device__ __forceinline__ void lds128(uint32_t* r, uint32_t addr) {
    asm volatile("ld.shared.v4.b32 {%0,%1,%2,%3}, [%4];"
                 : "=r"(r[0]), "=r"(r[1]), "=r"(r[2]), "=r"(r[3]) : "r"(addr));
}

// ---------------------------------------------------------------- prepasses
#define NA_BLOCKS 16384        // pack_A part
#define NW_BLOCKS 8192         // pack_W part
#define WLD 65                 // pack_W smem row stride

__device__ void pack_A_body(const float* __restrict__ x,
                            const float* __restrict__ h, int blk)
{
    uint32_t t = blk * 256 + threadIdx.x;
    int lane = t & 31;
    int mb = (t >> 5) & 255;
    int k8 = t >> 13;
    int kq = lane & 3, gq = lane >> 2;
    int m = mb * 16 + gq;
    int k = k8 * 8 + kq;
    const float* src = (k < UDIM) ? (x + k) : (h + (k - UDIM));
    uint4 u;
    u.x = tf32r(src[(size_t)m * UDIM]);
    u.y = tf32r(src[(size_t)(m + 8) * UDIM]);
    u.z = tf32r(src[(size_t)m * UDIM + 4]);
    u.w = tf32r(src[(size_t)(m + 8) * UDIM + 4]);
    *(uint4*)(g_Ap + (size_t)t * 4) = u;
}

__device__ void pack_W_body(
    uint32_t* s_w,
    const float* __restrict__ wxf, const float* __restrict__ wxi,
    const float* __restrict__ wxo, const float* __restrict__ wxg,
    const float* __restrict__ whf, const float* __restrict__ whi,
    const float* __restrict__ who, const float* __restrict__ whg, int blk)
{
    const int tid = threadIdx.x;
    const int kb = blk & 255;                // 256 k-blocks of 16
    const int ub = blk >> 8;                 // 32 unit-blocks of 64
    const int kbase = kb * 16;
    const int ubase = ub * 64;

    const bool isx = (kbase < UDIM);
    const int klocal = isx ? kbase : (kbase - UDIM);
    const float* Wg[4];
    Wg[0] = isx ? wxf : whf;
    Wg[1] = isx ? wxi : whi;
    Wg[2] = isx ? wxo : who;
    Wg[3] = isx ? wxg : whg;

    const int r = tid >> 4, q = tid & 15;
#pragma unroll
    for (int g = 0; g < 4; g++) {
        float4 v = *(const float4*)(Wg[g] + (size_t)(klocal + r) * UDIM +
                                    ubase + q * 4);
        uint32_t* d = s_w + (r * 4 + g) * WLD + q * 4;
        d[0] = tf32r(v.x); d[1] = tf32r(v.y);
        d[2] = tf32r(v.z); d[3] = tf32r(v.w);
    }
    __syncthreads();

#pragma unroll
    for (int i = 0; i < 4; i++) {
        int o = tid + 256 * i;
        int lane = o & 31;
        int nbpl = (o >> 5) & 15;
        int k8l = o >> 9;
        int kq = lane & 3, nq = lane >> 2;
        int g = nq & 3, b = nq >> 2;
        int ul = 4 * nbpl + b;
        int row0 = (k8l * 8 + kq) * 4 + g;
        int row1 = row0 + 16;
        uint4 v;
        v.x = s_w[row0 * WLD + ul];
        v.y = s_w[row1 * WLD + ul];
        v.z = s_w[row0 * WLD + ul + 2];
        v.w = s_w[row1 * WLD + ul + 2];
        int k8 = kb * 2 + k8l;
        int nbp = ub * 16 + nbpl;
        *(uint4*)(g_Bp + ((size_t)k8 * NBPTOT + nbp) * 128 + lane * 4) = v;
    }
}

__global__ void __launch_bounds__(256) pack_AW_kernel(
    const float* __restrict__ x, const float* __restrict__ h,
    const float* __restrict__ wxf, const float* __restrict__ wxi,
    const float* __restrict__ wxo, const float* __restrict__ wxg,
    const float* __restrict__ whf, const float* __restrict__ whi,
    const float* __restrict__ who, const float* __restrict__ whg)
{
    __shared__ uint32_t s_w[64 * WLD];
    if (blockIdx.x < NA_BLOCKS)
        pack_A_body(x, h, blockIdx.x);
    else
        pack_W_body(s_w, wxf, wxi, wxo, wxg, whf, whi, who, whg,
                    blockIdx.x - NA_BLOCKS);
}

// ---------------------------------------------------------------- GEMM
__device__ __forceinline__ void load_stage(uint32_t sbase, int slot, int kt,
                                           int tid, int mb0, int nbp0)
{
    uint32_t sa = sbase + slot * STAGE_BYTES;
    uint32_t sb = sa + SA_STAGE;
    const int k8 = kt * 4;
    const float* a0 = g_Ap + (size_t)k8 * (MBTOT * 128) + mb0 * 128;
    const float* b0 = g_Bp + (size_t)k8 * (NBPTOT * 128) + nbp0 * 128;
#pragma unroll
    for (int j = 0; j < 4; j++) {
        cp16(sa + j * 8192 + tid * 16,        a0 + (size_t)j * (MBTOT * 128) + tid * 4);
        cp16(sa + j * 8192 + 4096 + tid * 16, a0 + (size_t)j * (MBTOT * 128) + 1024 + tid * 4);
        cp16(sb + j * 4096 + tid * 16,        b0 + (size_t)j * (NBPTOT * 128) + tid * 4);
    }
}

__global__ void __launch_bounds__(NTHREADS, 1) lstm_gemm_kernel(
    const float* __restrict__ cin,
    const float* __restrict__ bfp, const float* __restrict__ bip,
    const float* __restrict__ bop, const float* __restrict__ bgp,
    float* __restrict__ out)
{
    extern __shared__ char smem[];
    const uint32_t sbase = smem_u32(smem);
    const int tid = threadIdx.x;
    const int wid = tid >> 5;
    const int lane = tid & 31;
    const int mt = blockIdx.x & 15;          // m fastest: A stays L2-resident
    const int nt = blockIdx.x >> 4;          // 0..63
    const int mb0 = mt * 16;
    const int nbp0 = nt * 8;

    const int wmi = wid & 3;                 // warp m index (64-row tile)
    const int wni = wid >> 2;                // warp n index (64-col tile)
    const uint32_t a_off = (uint32_t)wmi * 2048 + lane * 16;
    const uint32_t b_off = (uint32_t)wni * 2048 + lane * 16;

    float acc[4][8][4];
#pragma unroll
    for (int mf = 0; mf < 4; mf++)
#pragma unroll
        for (int nf = 0; nf < 8; nf++)
#pragma unroll
            for (int r = 0; r < 4; r++) acc[mf][nf][r] = 0.f;

    // prologue: 3 stages in flight
#pragma unroll
    for (int s = 0; s < 3; s++) {
        load_stage(sbase, s, s, tid, mb0, nbp0);
        cp_commit();
    }
    cp_wait<1>();            // stages 0 AND 1 complete (self)
    __syncthreads();         // visible to all

    uint32_t a[2][4][4];
    uint32_t b[2][8][2];

    // prime buffer 0 with (kt=0, ks=0) fragments
#pragma unroll
    for (int mf = 0; mf < 4; mf++)
        lds128(a[0][mf], sbase + mf * 512 + a_off);
#pragma unroll
    for (int p = 0; p < 4; p++)
        lds128(&b[0][2 * p][0], sbase + SA_STAGE + p * 512 + b_off);

    const int KT = KTOT / TK;                // 128
    for (int kt = 0; kt < KT; kt++) {
        const uint32_t sa = sbase + (kt & 3) * STAGE_BYTES;
        const uint32_t sb = sa + SA_STAGE;
        const uint32_t sa_n = sbase + ((kt + 1) & 3) * STAGE_BYTES;
        const uint32_t sb_n = sa_n + SA_STAGE;

        // Single barrier per kt (cutlass multistage ordering):
        //   wait first (stages kt, kt+1 complete on self), THEN barrier
        //   (cross-thread visibility + all readers past stage kt-1),
        //   THEN overwrite slot (kt-1)&3 with stage kt+3.
        if (kt > 0) {
            cp_wait<1>();
            __syncthreads();
        }
        if (kt + 3 < KT) {
            load_stage(sbase, (kt + 3) & 3, kt + 3, tid, mb0, nbp0);
            cp_commit();
        }

#pragma unroll
        for (int ks = 0; ks < 4; ks++) {
            const int cur = ks & 1, nxt = cur ^ 1;
            if (ks < 3) {        // prefetch next ks of this stage
#pragma unroll
                for (int mf = 0; mf < 4; mf++)
                    lds128(a[nxt][mf], sa + (ks + 1) * 8192 + mf * 512 + a_off);
#pragma unroll
                for (int p = 0; p < 4; p++)
                    lds128(&b[nxt][2 * p][0], sb + (ks + 1) * 4096 + p * 512 + b_off);
            } else if (kt + 1 < KT) {   // prefetch ks=0 of NEXT stage
#pragma unroll
                for (int mf = 0; mf < 4; mf++)
                    lds128(a[nxt][mf], sa_n + mf * 512 + a_off);
#pragma unroll
                for (int p = 0; p < 4; p++)
                    lds128(&b[nxt][2 * p][0], sb_n + p * 512 + b_off);
            }
#pragma unroll
            for (int mf = 0; mf < 4; mf++)
#pragma unroll
                for (int nf = 0; nf < 8; nf++)
                    mma8(acc[mf][nf], a[cur][mf], b[cur][nf]);
        }
    }

    cp_wait<0>();

    // ---- epilogue: two 128-row halves through smem ----
    float* s_z = (float*)smem;
    const int gq = lane >> 2, kq = lane & 3;
    const int m0 = mt * TM;
    const size_t HC = (size_t)MTOT * UDIM;
    const int ul = tid & 31;                 // unit lane (32 units per CTA)
    const int rb = tid >> 5;                 // 8 row blocks of 16 rows
    const int u = nt * 32 + ul;
    const float bf = __ldg(bfp + u);
    const float bi = __ldg(bip + u);
    const float bo = __ldg(bop + u);
    const float bg = __ldg(bgp + u);

#pragma unroll
    for (int hf = 0; hf < 2; hf++) {
        __syncthreads();   // pipeline done / previous half consumed
        if ((wmi >> 1) == hf) {
#pragma unroll
            for (int mf = 0; mf < 4; mf++)
#pragma unroll
                for (int nf = 0; nf < 8; nf++) {
                    int row = (wmi & 1) * 64 + mf * 16 + gq;
                    int col = wni * 64 + nf * 8 + 2 * kq;
                    *(float2*)(s_z + row * ZLD + col) =
                        make_float2(acc[mf][nf][0], acc[mf][nf][1]);
                    *(float2*)(s_z + (row + 8) * ZLD + col) =
                        make_float2(acc[mf][nf][2], acc[mf][nf][3]);
                }
        }
        __syncthreads();

#pragma unroll 4
        for (int rr = 0; rr < 16; rr++) {
            int row = rb * 16 + rr;
            float4 z = *(const float4*)(s_z + row * ZLD + 4 * ul);
            size_t g = (size_t)(m0 + hf * 128 + row) * UDIM + u;
            float zf = z.x + bf, zi = z.y + bi, zo = z.z + bo, zg = z.w + bg;
            float fg = 1.f / (1.f + expf(-zf));
            float ig = 1.f / (1.f + expf(-zi));
            float og = 1.f / (1.f + expf(-zo));
            float gg = tanhf(zg);
            float cn = fg * __ldg(cin + g) + ig * gg;
            float hn = og * tanhf(cn);
            __stcs(out + g, hn);          // h_new (streaming store)
            __stcs(out + HC + g, cn);     // c_new
        }
    }
}

// ---------------------------------------------------------------- launch
extern "C" void kernel_launch(void* const* d_in, const int* in_sizes, int n_in,
                              void* d_out, int out_size) {
    (void)in_sizes; (void)n_in; (void)out_size;
    const float* x   = (const float*)d_in[0];
    const float* h   = (const float*)d_in[1];
    const float* c   = (const float*)d_in[2];
    const float* Wxf = (const float*)d_in[3];
    const float* Wxi = (const float*)d_in[4];
    const float* Wxo = (const float*)d_in[5];
    const float* Wxg = (const float*)d_in[6];
    const float* bf  = (const float*)d_in[7];
    const float* bi  = (const float*)d_in[8];
    const float* bo  = (const float*)d_in[9];
    const float* bg  = (const float*)d_in[10];
    const float* Whf = (const float*)d_in[11];
    const float* Whi = (const float*)d_in[12];
    const float* Who = (const float*)d_in[13];
    const float* Whg = (const float*)d_in[14];
    float* out = (float*)d_out;

    static int smem_set = 0;
    if (!smem_set) {
        cudaFuncSetAttribute(lstm_gemm_kernel,
                             cudaFuncAttributeMaxDynamicSharedMemorySize,
                             SMEM_BYTES);
        smem_set = 1;
    }

    pack_AW_kernel<<<NA_BLOCKS + NW_BLOCKS, 256>>>(
        x, h, Wxf, Wxi, Wxo, Wxg, Whf, Whi, Who, Whg);
    lstm_gemm_kernel<<<(MTOT / TM) * (NTOT / TN), NTHREADS, SMEM_BYTES>>>(
        c, bf, bi, bo, bg, out);
}

// round 10
// speedup vs baseline: 1.0720x; 1.0720x over previous
#include <cuda_runtime.h>
#include <cstdint>

// ============================================================================
// LSTM cell, base sm_103 ISA. tf32 mma.sync m16n8k8, cp.async 4-stage TK=32,
// fragment-packed operands, register double-buffered fragments with
// cross-stage prefetch (R8 two-barrier mainloop — verified best).
// CTA 256x128, 256 threads, warp tile 64x64. Fused gate epilogue with
// streaming stores. Packs fused into one launch.
//
// z[4096, 8192] = A[4096, 4096] @ B[4096, 8192]
//   A = [x | h], B[k][4u+g] = W{x,h}{f,i,o,g}[k][u]  (gate-interleaved)
// ============================================================================

#define MTOT 4096
#define KTOT 4096
#define NTOT 8192
#define UDIM 2048

#define TM 256
#define TN 128
#define TK 32          // 4 k8 sub-steps per stage
#define STAGES 4
#define NTHREADS 256

#define MBTOT 256              // MTOT/16
#define NBPTOT 512             // NTOT/16 (n-fragment pairs)

#define SA_STAGE 32768         // 4 k8 * 16 mb * 512 B
#define SB_STAGE 16384         // 4 k8 * 8 nbp * 512 B
#define STAGE_BYTES (SA_STAGE + SB_STAGE)      // 49152
#define PIPE_BYTES (STAGES * STAGE_BYTES)      // 196608
#define ZLD 132
#define SMEM_BYTES PIPE_BYTES

// Fragment-packed tf32 operands.
// g_Ap[k8][mb][lane][4] : lane=(gq<<2)|kq holds A[mb*16+gq+{0,8}][k8*8+kq+{0,4}]
// g_Bp[k8][nbp][lane][4]: lane=(nq<<2)|kq holds B[k8*8+kq+{0,4}][nbp*16+nq+{0,8}]
static __device__ __align__(16) float g_Ap[(size_t)MTOT * KTOT];   // 64 MB
static __device__ __align__(16) float g_Bp[(size_t)KTOT * NTOT];   // 128 MB

// ---------------------------------------------------------------- helpers
__device__ __forceinline__ uint32_t smem_u32(const void* p) {
    uint32_t a;
    asm("{ .reg .u64 t; cvta.to.shared.u64 t, %1; cvt.u32.u64 %0, t; }"
        : "=r"(a) : "l"(p));
    return a;
}

__device__ __forceinline__ uint32_t tf32r(float v) {   // round-to-nearest tf32
    uint32_t r;
    asm("cvt.rna.tf32.f32 %0, %1;" : "=r"(r) : "f"(v));
    return r;
}

__device__ __forceinline__ void cp16(uint32_t dst, const void* src) {
    asm volatile("cp.async.cg.shared.global [%0], [%1], 16;"
                 :: "r"(dst), "l"(src) : "memory");
}
__device__ __forceinline__ void cp_commit() {
    asm volatile("cp.async.commit_group;" ::: "memory");
}
template <int N>
__device__ __forceinline__ void cp_wait() {
    asm volatile("cp.async.wait_group %0;" :: "n"(N) : "memory");
}

__device__ __forceinline__ void mma8(float* d, const uint32_t* a, const uint32_t* b) {
    asm volatile(
        "mma.sync.aligned.m16n8k8.row.col.f32.tf32.tf32.f32 "
        "{%0,%1,%2,%3}, {%4,%5,%6,%7}, {%8,%9}, {%0,%1,%2,%3};"
        : "+f"(d[0]), "+f"(d[1]), "+f"(d[2]), "+f"(d[3])
        : "r"(a[0]), "r"(a[1]), "r"(a[2]), "r"(a[3]), "r"(b[0]), "r"(b[1]));
}

__device__ __forceinline__ void lds128(uint32_t* r, uint32_t addr) {
    asm volatile("ld.shared.v4.b32 {%0,%1,%2,%3}, [%4];"
                 : "=r"(r[0]), "=r"(r[1]), "=r"(r[2]), "=r"(r[3]) : "r"(addr));
}

// ---------------------------------------------------------------- prepasses
#define NA_BLOCKS 16384        // pack_A part
#define NW_BLOCKS 8192         // pack_W part
#define WLD 65                 // pack_W smem row stride

__device__ void pack_A_body(const float* __restrict__ x,
                            const float* __restrict__ h, int blk)
{
    uint32_t t = blk * 256 + threadIdx.x;
    int lane = t & 31;
    int mb = (t >> 5) & 255;
    int k8 = t >> 13;
    int kq = lane & 3, gq = lane >> 2;
    int m = mb * 16 + gq;
    int k = k8 * 8 + kq;
    const float* src = (k < UDIM) ? (x + k) : (h + (k - UDIM));
    uint4 u;
    u.x = tf32r(src[(size_t)m * UDIM]);
    u.y = tf32r(src[(size_t)(m + 8) * UDIM]);
    u.z = tf32r(src[(size_t)m * UDIM + 4]);
    u.w = tf32r(src[(size_t)(m + 8) * UDIM + 4]);
    *(uint4*)(g_Ap + (size_t)t * 4) = u;
}

__device__ void pack_W_body(
    uint32_t* s_w,
    const float* __restrict__ wxf, const float* __restrict__ wxi,
    const float* __restrict__ wxo, const float* __restrict__ wxg,
    const float* __restrict__ whf, const float* __restrict__ whi,
    const float* __restrict__ who, const float* __restrict__ whg, int blk)
{
    const int tid = threadIdx.x;
    const int kb = blk & 255;                // 256 k-blocks of 16
    const int ub = blk >> 8;                 // 32 unit-blocks of 64
    const int kbase = kb * 16;
    const int ubase = ub * 64;

    const bool isx = (kbase < UDIM);
    const int klocal = isx ? kbase : (kbase - UDIM);
    const float* Wg[4];
    Wg[0] = isx ? wxf : whf;
    Wg[1] = isx ? wxi : whi;
    Wg[2] = isx ? wxo : who;
    Wg[3] = isx ? wxg : whg;

    const int r = tid >> 4, q = tid & 15;
#pragma unroll
    for (int g = 0; g < 4; g++) {
        float4 v = *(const float4*)(Wg[g] + (size_t)(klocal + r) * UDIM +
                                    ubase + q * 4);
        uint32_t* d = s_w + (r * 4 + g) * WLD + q * 4;
        d[0] = tf32r(v.x); d[1] = tf32r(v.y);
        d[2] = tf32r(v.z); d[3] = tf32r(v.w);
    }
    __syncthreads();

#pragma unroll
    for (int i = 0; i < 4; i++) {
        int o = tid + 256 * i;
        int lane = o & 31;
        int nbpl = (o >> 5) & 15;
        int k8l = o >> 9;
        int kq = lane & 3, nq = lane >> 2;
        int g = nq & 3, b = nq >> 2;
        int ul = 4 * nbpl + b;
        int row0 = (k8l * 8 + kq) * 4 + g;
        int row1 = row0 + 16;
        uint4 v;
        v.x = s_w[row0 * WLD + ul];
        v.y = s_w[row1 * WLD + ul];
        v.z = s_w[row0 * WLD + ul + 2];
        v.w = s_w[row1 * WLD + ul + 2];
        int k8 = kb * 2 + k8l;
        int nbp = ub * 16 + nbpl;
        *(uint4*)(g_Bp + ((size_t)k8 * NBPTOT + nbp) * 128 + lane * 4) = v;
    }
}

__global__ void __launch_bounds__(256) pack_AW_kernel(
    const float* __restrict__ x, const float* __restrict__ h,
    const float* __restrict__ wxf, const float* __restrict__ wxi,
    const float* __restrict__ wxo, const float* __restrict__ wxg,
    const float* __restrict__ whf, const float* __restrict__ whi,
    const float* __restrict__ who, const float* __restrict__ whg)
{
    __shared__ uint32_t s_w[64 * WLD];
    if (blockIdx.x < NA_BLOCKS)
        pack_A_body(x, h, blockIdx.x);
    else
        pack_W_body(s_w, wxf, wxi, wxo, wxg, whf, whi, who, whg,
                    blockIdx.x - NA_BLOCKS);
}

// ---------------------------------------------------------------- GEMM
__device__ __forceinline__ void load_stage(uint32_t sbase, int slot, int kt,
                                           int tid, int mb0, int nbp0)
{
    uint32_t sa = sbase + slot * STAGE_BYTES;
    uint32_t sb = sa + SA_STAGE;
    const int k8 = kt * 4;
    const float* a0 = g_Ap + (size_t)k8 * (MBTOT * 128) + mb0 * 128;
    const float* b0 = g_Bp + (size_t)k8 * (NBPTOT * 128) + nbp0 * 128;
#pragma unroll
    for (int j = 0; j < 4; j++) {
        cp16(sa + j * 8192 + tid * 16,        a0 + (size_t)j * (MBTOT * 128) + tid * 4);
        cp16(sa + j * 8192 + 4096 + tid * 16, a0 + (size_t)j * (MBTOT * 128) + 1024 + tid * 4);
        cp16(sb + j * 4096 + tid * 16,        b0 + (size_t)j * (NBPTOT * 128) + tid * 4);
    }
}

__global__ void __launch_bounds__(NTHREADS, 1) lstm_gemm_kernel(
    const float* __restrict__ cin,
    const float* __restrict__ bfp, const float* __restrict__ bip,
    const float* __restrict__ bop, const float* __restrict__ bgp,
    float* __restrict__ out)
{
    extern __shared__ char smem[];
    const uint32_t sbase = smem_u32(smem);
    const int tid = threadIdx.x;
    const int wid = tid >> 5;
    const int lane = tid & 31;
    const int mt = blockIdx.x & 15;          // m fastest: A stays L2-resident
    const int nt = blockIdx.x >> 4;          // 0..63
    const int mb0 = mt * 16;
    const int nbp0 = nt * 8;

    const int wmi = wid & 3;                 // warp m index (64-row tile)
    const int wni = wid >> 2;                // warp n index (64-col tile)
    const uint32_t a_off = (uint32_t)wmi * 2048 + lane * 16;
    const uint32_t b_off = (uint32_t)wni * 2048 + lane * 16;

    float acc[4][8][4];
#pragma unroll
    for (int mf = 0; mf < 4; mf++)
#pragma unroll
        for (int nf = 0; nf < 8; nf++)
#pragma unroll
            for (int r = 0; r < 4; r++) acc[mf][nf][r] = 0.f;

    // prologue: 3 stages in flight
#pragma unroll
    for (int s = 0; s < 3; s++) {
        load_stage(sbase, s, s, tid, mb0, nbp0);
        cp_commit();
    }
    cp_wait<2>();            // stage 0 complete (self)
    __syncthreads();         // visible to all

    uint32_t a[2][4][4];
    uint32_t b[2][8][2];

    // prime buffer 0 with (kt=0, ks=0) fragments
#pragma unroll
    for (int mf = 0; mf < 4; mf++)
        lds128(a[0][mf], sbase + mf * 512 + a_off);
#pragma unroll
    for (int p = 0; p < 4; p++)
        lds128(&b[0][2 * p][0], sbase + SA_STAGE + p * 512 + b_off);

    const int KT = KTOT / TK;                // 128
    for (int kt = 0; kt < KT; kt++) {
        const uint32_t sa = sbase + (kt & 3) * STAGE_BYTES;
        const uint32_t sb = sa + SA_STAGE;
        const uint32_t sa_n = sbase + ((kt + 1) & 3) * STAGE_BYTES;
        const uint32_t sb_n = sa_n + SA_STAGE;

        __syncthreads();                     // (A) readers of old slot done
        if (kt + 3 < KT) load_stage(sbase, (kt + 3) & 3, kt + 3, tid, mb0, nbp0);
        cp_commit();
        cp_wait<2>();                        // stage kt+1 complete (self)
        __syncthreads();                     // (B) stage kt+1 visible to all

#pragma unroll
        for (int ks = 0; ks < 4; ks++) {
            const int cur = ks & 1, nxt = cur ^ 1;
            if (ks < 3) {        // prefetch next ks of this stage
#pragma unroll
                for (int mf = 0; mf < 4; mf++)
                    lds128(a[nxt][mf], sa + (ks + 1) * 8192 + mf * 512 + a_off);
#pragma unroll
                for (int p = 0; p < 4; p++)
                    lds128(&b[nxt][2 * p][0], sb + (ks + 1) * 4096 + p * 512 + b_off);
            } else if (kt + 1 < KT) {   // prefetch ks=0 of NEXT stage
#pragma unroll
                for (int mf = 0; mf < 4; mf++)
                    lds128(a[nxt][mf], sa_n + mf * 512 + a_off);
#pragma unroll
                for (int p = 0; p < 4; p++)
                    lds128(&b[nxt][2 * p][0], sb_n + p * 512 + b_off);
            }
#pragma unroll
            for (int mf = 0; mf < 4; mf++)
#pragma unroll
                for (int nf = 0; nf < 8; nf++)
                    mma8(acc[mf][nf], a[cur][mf], b[cur][nf]);
        }
    }

    cp_wait<0>();

    // ---- epilogue: two 128-row halves through smem ----
    float* s_z = (float*)smem;
    const int gq = lane >> 2, kq = lane & 3;
    const int m0 = mt * TM;
    const size_t HC = (size_t)MTOT * UDIM;
    const int ul = tid & 31;                 // unit lane (32 units per CTA)
    const int rb = tid >> 5;                 // 8 row blocks of 16 rows
    const int u = nt * 32 + ul;
    const float bf = __ldg(bfp + u);
    const float bi = __ldg(bip + u);
    const float bo = __ldg(bop + u);
    const float bg = __ldg(bgp + u);

#pragma unroll
    for (int hf = 0; hf < 2; hf++) {
        __syncthreads();   // pipeline done / previous half consumed
        if ((wmi >> 1) == hf) {
#pragma unroll
            for (int mf = 0; mf < 4; mf++)
#pragma unroll
                for (int nf = 0; nf < 8; nf++) {
                    int row = (wmi & 1) * 64 + mf * 16 + gq;
                    int col = wni * 64 + nf * 8 + 2 * kq;
                    *(float2*)(s_z + row * ZLD + col) =
                        make_float2(acc[mf][nf][0], acc[mf][nf][1]);
                    *(float2*)(s_z + (row + 8) * ZLD + col) =
                        make_float2(acc[mf][nf][2], acc[mf][nf][3]);
                }
        }
        __syncthreads();

#pragma unroll 4
        for (int rr = 0; rr < 16; rr++) {
            int row = rb * 16 + rr;
            float4 z = *(const float4*)(s_z + row * ZLD + 4 * ul);
            size_t g = (size_t)(m0 + hf * 128 + row) * UDIM + u;
            float zf = z.x + bf, zi = z.y + bi, zo = z.z + bo, zg = z.w + bg;
            float fg = 1.f / (1.f + expf(-zf));
            float ig = 1.f / (1.f + expf(-zi));
            float og = 1.f / (1.f + expf(-zo));
            float gg = tanhf(zg);
            float cn = fg * __ldcs(cin + g) + ig * gg;   // streaming load
            float hn = og * tanhf(cn);
            __stcs(out + g, hn);          // h_new (streaming store)
            __stcs(out + HC + g, cn);     // c_new
        }
    }
}

// ---------------------------------------------------------------- launch
extern "C" void kernel_launch(void* const* d_in, const int* in_sizes, int n_in,
                              void* d_out, int out_size) {
    (void)in_sizes; (void)n_in; (void)out_size;
    const float* x   = (const float*)d_in[0];
    const float* h   = (const float*)d_in[1];
    const float* c   = (const float*)d_in[2];
    const float* Wxf = (const float*)d_in[3];
    const float* Wxi = (const float*)d_in[4];
    const float* Wxo = (const float*)d_in[5];
    const float* Wxg = (const float*)d_in[6];
    const float* bf  = (const float*)d_in[7];
    const float* bi  = (const float*)d_in[8];
    const float* bo  = (const float*)d_in[9];
    const float* bg  = (const float*)d_in[10];
    const float* Whf = (const float*)d_in[11];
    const float* Whi = (const float*)d_in[12];
    const float* Who = (const float*)d_in[13];
    const float* Whg = (const float*)d_in[14];
    float* out = (float*)d_out;

    static int smem_set = 0;
    if (!smem_set) {
        cudaFuncSetAttribute(lstm_gemm_kernel,
                             cudaFuncAttributeMaxDynamicSharedMemorySize,
                             SMEM_BYTES);
        smem_set = 1;
    }

    pack_AW_kernel<<<NA_BLOCKS + NW_BLOCKS, 256>>>(
        x, h, Wxf, Wxi, Wxo, Wxg, Whf, Whi, Who, Whg);
    lstm_gemm_kernel<<<(MTOT / TM) * (NTOT / TN), NTHREADS, SMEM_BYTES>>>(
        c, bf, bi, bo, bg, out);
}

// round 11
// speedup vs baseline: 1.1885x; 1.1087x over previous
#include <cuda_runtime.h>
#include <cstdint>

// ============================================================================
// LSTM cell, base sm_103 ISA. tf32 mma.sync m16n8k8, cp.async 3-stage TK=32,
// fragment-packed operands, register double-buffered fragments with
// cross-stage prefetch. CTA 128x128 with 128 threads, warp tile 64x64,
// 2 CTAs/SM (barrier bubbles hidden by co-resident CTA). Fused gate epilogue.
//
// z[4096, 8192] = A[4096, 4096] @ B[4096, 8192]
//   A = [x | h], B[k][4u+g] = W{x,h}{f,i,o,g}[k][u]  (gate-interleaved)
// ============================================================================

#define MTOT 4096
#define KTOT 4096
#define NTOT 8192
#define UDIM 2048

#define TM 128
#define TN 128
#define TK 32          // 4 k8 sub-steps per stage
#define STAGES 3
#define NTHREADS 128

#define MBTOT 256              // MTOT/16
#define NBPTOT 512             // NTOT/16 (n-fragment pairs)

#define SA_STAGE 16384         // 4 k8 * 8 mb * 512 B
#define SB_STAGE 16384         // 4 k8 * 8 nbp * 512 B
#define STAGE_BYTES (SA_STAGE + SB_STAGE)      // 32768
#define PIPE_BYTES (STAGES * STAGE_BYTES)      // 98304
#define ZLD 132                                 // z tile: 128*132*4 = 67584
#define SMEM_BYTES PIPE_BYTES

// Fragment-packed tf32 operands.
// g_Ap[k8][mb][lane][4] : lane=(gq<<2)|kq holds A[mb*16+gq+{0,8}][k8*8+kq+{0,4}]
// g_Bp[k8][nbp][lane][4]: lane=(nq<<2)|kq holds B[k8*8+kq+{0,4}][nbp*16+nq+{0,8}]
static __device__ __align__(16) float g_Ap[(size_t)MTOT * KTOT];   // 64 MB
static __device__ __align__(16) float g_Bp[(size_t)KTOT * NTOT];   // 128 MB

// ---------------------------------------------------------------- helpers
__device__ __forceinline__ uint32_t smem_u32(const void* p) {
    uint32_t a;
    asm("{ .reg .u64 t; cvta.to.shared.u64 t, %1; cvt.u32.u64 %0, t; }"
        : "=r"(a) : "l"(p));
    return a;
}

__device__ __forceinline__ uint32_t tf32r(float v) {   // round-to-nearest tf32
    uint32_t r;
    asm("cvt.rna.tf32.f32 %0, %1;" : "=r"(r) : "f"(v));
    return r;
}

__device__ __forceinline__ void cp16(uint32_t dst, const void* src) {
    asm volatile("cp.async.cg.shared.global [%0], [%1], 16;"
                 :: "r"(dst), "l"(src) : "memory");
}
__device__ __forceinline__ void cp_commit() {
    asm volatile("cp.async.commit_group;" ::: "memory");
}
template <int N>
__device__ __forceinline__ void cp_wait() {
    asm volatile("cp.async.wait_group %0;" :: "n"(N) : "memory");
}

__device__ __forceinline__ void mma8(float* d, const uint32_t* a, const uint32_t* b) {
    asm volatile(
        "mma.sync.aligned.m16n8k8.row.col.f32.tf32.tf32.f32 "
        "{%0,%1,%2,%3}, {%4,%5,%6,%7}, {%8,%9}, {%0,%1,%2,%3};"
        : "+f"(d[0]), "+f"(d[1]), "+f"(d[2]), "+f"(d[3])
        : "r"(a[0]), "r"(a[1]), "r"(a[2]), "r"(a[3]), "r"(b[0]), "r"(b[1]));
}

__device__ __forceinline__ void lds128(uint32_t* r, uint32_t addr) {
    asm volatile("ld.shared.v4.b32 {%0,%1,%2,%3}, [%4];"
                 : "=r"(r[0]), "=r"(r[1]), "=r"(r[2]), "=r"(r[3]) : "r"(addr));
}

// ---------------------------------------------------------------- prepasses
#define NA_BLOCKS 16384        // pack_A part
#define NW_BLOCKS 8192         // pack_W part
#define WLD 65                 // pack_W smem row stride

__device__ void pack_A_body(const float* __restrict__ x,
                            const float* __restrict__ h, int blk)
{
    uint32_t t = blk * 256 + threadIdx.x;
    int lane = t & 31;
    int mb = (t >> 5) & 255;
    int k8 = t >> 13;
    int kq = lane & 3, gq = lane >> 2;
    int m = mb * 16 + gq;
    int k = k8 * 8 + kq;
    const float* src = (k < UDIM) ? (x + k) : (h + (k - UDIM));
    uint4 u;
    u.x = tf32r(src[(size_t)m * UDIM]);
    u.y = tf32r(src[(size_t)(m + 8) * UDIM]);
    u.z = tf32r(src[(size_t)m * UDIM + 4]);
    u.w = tf32r(src[(size_t)(m + 8) * UDIM + 4]);
    *(uint4*)(g_Ap + (size_t)t * 4) = u;
}

__device__ void pack_W_body(
    uint32_t* s_w,
    const float* __restrict__ wxf, const float* __restrict__ wxi,
    const float* __restrict__ wxo, const float* __restrict__ wxg,
    const float* __restrict__ whf, const float* __restrict__ whi,
    const float* __restrict__ who, const float* __restrict__ whg, int blk)
{
    const int tid = threadIdx.x;
    const int kb = blk & 255;                // 256 k-blocks of 16
    const int ub = blk >> 8;                 // 32 unit-blocks of 64
    const int kbase = kb * 16;
    const int ubase = ub * 64;

    const bool isx = (kbase < UDIM);
    const int klocal = isx ? kbase : (kbase - UDIM);
    const float* Wg[4];
    Wg[0] = isx ? wxf : whf;
    Wg[1] = isx ? wxi : whi;
    Wg[2] = isx ? wxo : who;
    Wg[3] = isx ? wxg : whg;

    const int r = tid >> 4, q = tid & 15;
#pragma unroll
    for (int g = 0; g < 4; g++) {
        float4 v = *(const float4*)(Wg[g] + (size_t)(klocal + r) * UDIM +
                                    ubase + q * 4);
        uint32_t* d = s_w + (r * 4 + g) * WLD + q * 4;
        d[0] = tf32r(v.x); d[1] = tf32r(v.y);
        d[2] = tf32r(v.z); d[3] = tf32r(v.w);
    }
    __syncthreads();

#pragma unroll
    for (int i = 0; i < 4; i++) {
        int o = tid + 256 * i;
        int lane = o & 31;
        int nbpl = (o >> 5) & 15;
        int k8l = o >> 9;
        int kq = lane & 3, nq = lane >> 2;
        int g = nq & 3, b = nq >> 2;
        int ul = 4 * nbpl + b;
        int row0 = (k8l * 8 + kq) * 4 + g;
        int row1 = row0 + 16;
        uint4 v;
        v.x = s_w[row0 * WLD + ul];
        v.y = s_w[row1 * WLD + ul];
        v.z = s_w[row0 * WLD + ul + 2];
        v.w = s_w[row1 * WLD + ul + 2];
        int k8 = kb * 2 + k8l;
        int nbp = ub * 16 + nbpl;
        *(uint4*)(g_Bp + ((size_t)k8 * NBPTOT + nbp) * 128 + lane * 4) = v;
    }
}

__global__ void __launch_bounds__(256) pack_AW_kernel(
    const float* __restrict__ x, const float* __restrict__ h,
    const float* __restrict__ wxf, const float* __restrict__ wxi,
    const float* __restrict__ wxo, const float* __restrict__ wxg,
    const float* __restrict__ whf, const float* __restrict__ whi,
    const float* __restrict__ who, const float* __restrict__ whg)
{
    __shared__ uint32_t s_w[64 * WLD];
    if (blockIdx.x < NA_BLOCKS)
        pack_A_body(x, h, blockIdx.x);
    else
        pack_W_body(s_w, wxf, wxi, wxo, wxg, whf, whi, who, whg,
                    blockIdx.x - NA_BLOCKS);
}

// ---------------------------------------------------------------- GEMM
#define AK8 (MBTOT * 128)      // per-k8 float stride in g_Ap
#define BK8 (NBPTOT * 128)     // per-k8 float stride in g_Bp

__device__ __forceinline__ void load_stage(uint32_t sbase, int slot, int kt,
                                           int tid, int mb0, int nbp0)
{
    uint32_t sa = sbase + slot * STAGE_BYTES;
    uint32_t sb = sa + SA_STAGE;
    const int k8 = kt * 4;
    const float* a0 = g_Ap + (size_t)k8 * AK8 + mb0 * 128;
    const float* b0 = g_Bp + (size_t)k8 * BK8 + nbp0 * 128;
#pragma unroll
    for (int j = 0; j < 4; j++) {          // 4 k8 slabs, 4KB each operand
        cp16(sa + j * 4096 + tid * 16,        a0 + (size_t)j * AK8 + tid * 4);
        cp16(sa + j * 4096 + 2048 + tid * 16, a0 + (size_t)j * AK8 + 512 + tid * 4);
        cp16(sb + j * 4096 + tid * 16,        b0 + (size_t)j * BK8 + tid * 4);
        cp16(sb + j * 4096 + 2048 + tid * 16, b0 + (size_t)j * BK8 + 512 + tid * 4);
    }
}

__global__ void __launch_bounds__(NTHREADS, 2) lstm_gemm_kernel(
    const float* __restrict__ cin,
    const float* __restrict__ bfp, const float* __restrict__ bip,
    const float* __restrict__ bop, const float* __restrict__ bgp,
    float* __restrict__ out)
{
    extern __shared__ char smem[];
    const uint32_t sbase = smem_u32(smem);
    const int tid = threadIdx.x;
    const int wid = tid >> 5;
    const int lane = tid & 31;
    const int mt = blockIdx.x & 31;          // m fastest: A stays L2-resident
    const int nt = blockIdx.x >> 5;          // 0..63
    const int mb0 = mt * 8;
    const int nbp0 = nt * 8;

    const int wmi = wid & 1;                 // warp m index (64-row tile)
    const int wni = wid >> 1;                // warp n index (64-col tile)
    const uint32_t a_off = (uint32_t)wmi * 2048 + lane * 16;
    const uint32_t b_off = (uint32_t)wni * 2048 + lane * 16;

    float acc[4][8][4];
#pragma unroll
    for (int mf = 0; mf < 4; mf++)
#pragma unroll
        for (int nf = 0; nf < 8; nf++)
#pragma unroll
            for (int r = 0; r < 4; r++) acc[mf][nf][r] = 0.f;

    // prologue: 2 stages in flight
    load_stage(sbase, 0, 0, tid, mb0, nbp0);
    cp_commit();
    load_stage(sbase, 1, 1, tid, mb0, nbp0);
    cp_commit();
    cp_wait<1>();            // stage 0 complete (self)
    __syncthreads();         // visible to all

    uint32_t a[2][4][4];
    uint32_t b[2][8][2];

    // prime buffer 0 with (kt=0, ks=0) fragments
#pragma unroll
    for (int mf = 0; mf < 4; mf++)
        lds128(a[0][mf], sbase + mf * 512 + a_off);
#pragma unroll
    for (int p = 0; p < 4; p++)
        lds128(&b[0][2 * p][0], sbase + SA_STAGE + p * 512 + b_off);

    const int KT = KTOT / TK;                // 128
    int cs = 0, ls = 2;                      // compute slot, load slot
    for (int kt = 0; kt < KT; kt++) {
        const uint32_t sa = sbase + cs * STAGE_BYTES;
        const uint32_t sb = sa + SA_STAGE;
        const int ns = (cs == 2) ? 0 : cs + 1;
        const uint32_t sa_n = sbase + ns * STAGE_BYTES;
        const uint32_t sb_n = sa_n + SA_STAGE;

        __syncthreads();                     // (A) readers of old slot done
        if (kt + 2 < KT) load_stage(sbase, ls, kt + 2, tid, mb0, nbp0);
        cp_commit();
        cp_wait<1>();                        // stage kt+1 complete (self)
        __syncthreads();                     // (B) stage kt+1 visible to all

#pragma unroll
        for (int ks = 0; ks < 4; ks++) {
            const int cur = ks & 1, nxt = cur ^ 1;
            if (ks < 3) {        // prefetch next ks of this stage
#pragma unroll
                for (int mf = 0; mf < 4; mf++)
                    lds128(a[nxt][mf], sa + (ks + 1) * 4096 + mf * 512 + a_off);
#pragma unroll
                for (int p = 0; p < 4; p++)
                    lds128(&b[nxt][2 * p][0], sb + (ks + 1) * 4096 + p * 512 + b_off);
            } else if (kt + 1 < KT) {   // prefetch ks=0 of NEXT stage
#pragma unroll
                for (int mf = 0; mf < 4; mf++)
                    lds128(a[nxt][mf], sa_n + mf * 512 + a_off);
#pragma unroll
                for (int p = 0; p < 4; p++)
                    lds128(&b[nxt][2 * p][0], sb_n + p * 512 + b_off);
            }
#pragma unroll
            for (int mf = 0; mf < 4; mf++)
#pragma unroll
                for (int nf = 0; nf < 8; nf++)
                    mma8(acc[mf][nf], a[cur][mf], b[cur][nf]);
        }

        cs = ns;
        ls = (ls == 2) ? 0 : ls + 1;
    }

    cp_wait<0>();
    __syncthreads();     // pipeline done; reuse smem for z tile

    // ---- epilogue: single 128x128 z tile through smem ----
    float* s_z = (float*)smem;
    const int gq = lane >> 2, kq = lane & 3;
    const int m0 = mt * TM;
    const size_t HC = (size_t)MTOT * UDIM;

#pragma unroll
    for (int mf = 0; mf < 4; mf++)
#pragma unroll
        for (int nf = 0; nf < 8; nf++) {
            int row = wmi * 64 + mf * 16 + gq;
            int col = wni * 64 + nf * 8 + 2 * kq;
            *(float2*)(s_z + row * ZLD + col) =
                make_float2(acc[mf][nf][0], acc[mf][nf][1]);
            *(float2*)(s_z + (row + 8) * ZLD + col) =
                make_float2(acc[mf][nf][2], acc[mf][nf][3]);
        }
    __syncthreads();

    const int ul = tid & 31;                 // unit lane (32 units per CTA)
    const int rb = tid >> 5;                 // 4 row blocks of 32 rows
    const int u = nt * 32 + ul;
    const float bf = __ldg(bfp + u);
    const float bi = __ldg(bip + u);
    const float bo = __ldg(bop + u);
    const float bg = __ldg(bgp + u);

#pragma unroll 4
    for (int rr = 0; rr < 32; rr++) {
        int row = rb * 32 + rr;
        float4 z = *(const float4*)(s_z + row * ZLD + 4 * ul);
        size_t g = (size_t)(m0 + row) * UDIM + u;
        float zf = z.x + bf, zi = z.y + bi, zo = z.z + bo, zg = z.w + bg;
        float fg = 1.f / (1.f + expf(-zf));
        float ig = 1.f / (1.f + expf(-zi));
        float og = 1.f / (1.f + expf(-zo));
        float gg = tanhf(zg);
        float cn = fg * __ldcs(cin + g) + ig * gg;
        float hn = og * tanhf(cn);
        __stcs(out + g, hn);          // h_new (streaming store)
        __stcs(out + HC + g, cn);     // c_new
    }
}

// ---------------------------------------------------------------- launch
extern "C" void kernel_launch(void* const* d_in, const int* in_sizes, int n_in,
                              void* d_out, int out_size) {
    (void)in_sizes; (void)n_in; (void)out_size;
    const float* x   = (const float*)d_in[0];
    const float* h   = (const float*)d_in[1];
    const float* c   = (const float*)d_in[2];
    const float* Wxf = (const float*)d_in[3];
    const float* Wxi = (const float*)d_in[4];
    const float* Wxo = (const float*)d_in[5];
    const float* Wxg = (const float*)d_in[6];
    const float* bf  = (const float*)d_in[7];
    const float* bi  = (const float*)d_in[8];
    const float* bo  = (const float*)d_in[9];
    const float* bg  = (const float*)d_in[10];
    const float* Whf = (const float*)d_in[11];
    const float* Whi = (const float*)d_in[12];
    const float* Who = (const float*)d_in[13];
    const float* Whg = (const float*)d_in[14];
    float* out = (float*)d_out;

    static int smem_set = 0;
    if (!smem_set) {
        cudaFuncSetAttribute(lstm_gemm_kernel,
                             cudaFuncAttributeMaxDynamicSharedMemorySize,
                             SMEM_BYTES);
        smem_set = 1;
    }

    pack_AW_kernel<<<NA_BLOCKS + NW_BLOCKS, 256>>>(
        x, h, Wxf, Wxi, Wxo, Wxg, Whf, Whi, Who, Whg);
    lstm_gemm_kernel<<<(MTOT / TM) * (NTOT / TN), NTHREADS, SMEM_BYTES>>>(
        c, bf, bi, bo, bg, out);
}

// round 12
// speedup vs baseline: 2.1693x; 1.8252x over previous
#include <cuda_runtime.h>
#include <cuda_fp16.h>
#include <cstdint>

// ============================================================================
// LSTM cell, base sm_103 ISA. *** fp16 *** mma.sync m16n8k16 (same 10-bit
// mantissa as tf32, 2x MACs/instr), cp.async 3-stage TK=64, fragment-packed
// operands, register double-buffered fragments with cross-stage prefetch.
// CTA 128x128, 128 threads, warp tile 64x64, 2 CTAs/SM. Fused gate epilogue.
//
// z[4096, 8192] = A[4096, 4096] @ B[4096, 8192]
//   A = [x | h], B[k][4u+g] = W{x,h}{f,i,o,g}[k][u]  (gate-interleaved)
// ============================================================================

#define MTOT 4096
#define KTOT 4096
#define NTOT 8192
#define UDIM 2048

#define TM 128
#define TN 128
#define TK 64          // 4 k16 sub-steps per stage
#define STAGES 3
#define NTHREADS 128

#define MBTOT 256              // MTOT/16
#define NBPTOT 512             // NTOT/16 (n-fragment pairs)
#define K16TOT 256             // KTOT/16

#define AK16 (MBTOT * 128)     // uint32 stride per k16 in g_Ap
#define BK16 (NBPTOT * 128)    // uint32 stride per k16 in g_Bp

#define SA_STAGE 16384         // 4 k16 * 8 mb * 512 B
#define SB_STAGE 16384         // 4 k16 * 8 nbp * 512 B
#define STAGE_BYTES (SA_STAGE + SB_STAGE)      // 32768
#define PIPE_BYTES (STAGES * STAGE_BYTES)      // 98304
#define ZLD 132                                 // z tile: 128*132*4 = 67584
#define SMEM_BYTES PIPE_BYTES

// Fragment-packed fp16 operands (uint32 = f16x2).
// g_Ap[k16][mb][lane][4] : lane=(gq<<2)|kq holds
//   A[mb*16+gq+{0,8}][k16*16 + 2kq+{0,1}] and [.. + 2kq+8+{0,1}]
// g_Bp[k16][nbp][lane][4]: lane=(nq<<2)|kq holds
//   B[k16*16+2kq+{0,1,8,9}][nbp*16+nq+{0,8}]
static __device__ __align__(16) uint32_t g_Ap[(size_t)K16TOT * AK16];  // 32 MB
static __device__ __align__(16) uint32_t g_Bp[(size_t)K16TOT * BK16];  // 64 MB

// ---------------------------------------------------------------- helpers
__device__ __forceinline__ uint32_t smem_u32(const void* p) {
    uint32_t a;
    asm("{ .reg .u64 t; cvta.to.shared.u64 t, %1; cvt.u32.u64 %0, t; }"
        : "=r"(a) : "l"(p));
    return a;
}

__device__ __forceinline__ uint32_t packh2(float lo, float hi) {
    __half2 h = __floats2half2_rn(lo, hi);       // lo -> low 16 bits
    return *reinterpret_cast<uint32_t*>(&h);
}

__device__ __forceinline__ void cp16(uint32_t dst, const void* src) {
    asm volatile("cp.async.cg.shared.global [%0], [%1], 16;"
                 :: "r"(dst), "l"(src) : "memory");
}
__device__ __forceinline__ void cp_commit() {
    asm volatile("cp.async.commit_group;" ::: "memory");
}
template <int N>
__device__ __forceinline__ void cp_wait() {
    asm volatile("cp.async.wait_group %0;" :: "n"(N) : "memory");
}

__device__ __forceinline__ void mma16(float* d, const uint32_t* a, const uint32_t* b) {
    asm volatile(
        "mma.sync.aligned.m16n8k16.row.col.f32.f16.f16.f32 "
        "{%0,%1,%2,%3}, {%4,%5,%6,%7}, {%8,%9}, {%0,%1,%2,%3};"
        : "+f"(d[0]), "+f"(d[1]), "+f"(d[2]), "+f"(d[3])
        : "r"(a[0]), "r"(a[1]), "r"(a[2]), "r"(a[3]), "r"(b[0]), "r"(b[1]));
}

__device__ __forceinline__ void lds128(uint32_t* r, uint32_t addr) {
    asm volatile("ld.shared.v4.b32 {%0,%1,%2,%3}, [%4];"
                 : "=r"(r[0]), "=r"(r[1]), "=r"(r[2]), "=r"(r[3]) : "r"(addr));
}

// ---------------------------------------------------------------- prepasses
#define NA_BLOCKS 8192         // pack_A: 256 k16 * 256 mb * 32 / 256
#define NW_BLOCKS 8192         // pack_W: 256 kb * 32 ub
#define WLD 65                 // pack_W smem row stride

__device__ void pack_A_body(const float* __restrict__ x,
                            const float* __restrict__ h, int blk)
{
    uint32_t t = blk * 256 + threadIdx.x;
    int lane = t & 31;
    int mb = (t >> 5) & 255;
    int k16 = t >> 13;                   // 0..255
    int kq = lane & 3, gq = lane >> 2;
    int m = mb * 16 + gq;
    int k = k16 * 16 + 2 * kq;
    const float* src = (k < UDIM) ? (x + k) : (h + (k - UDIM));
    float2 p0 = *(const float2*)(src + (size_t)m * UDIM);
    float2 p1 = *(const float2*)(src + (size_t)(m + 8) * UDIM);
    float2 p2 = *(const float2*)(src + (size_t)m * UDIM + 8);
    float2 p3 = *(const float2*)(src + (size_t)(m + 8) * UDIM + 8);
    uint4 u;
    u.x = packh2(p0.x, p0.y);
    u.y = packh2(p1.x, p1.y);
    u.z = packh2(p2.x, p2.y);
    u.w = packh2(p3.x, p3.y);
    *(uint4*)(g_Ap + (size_t)t * 4) = u;
}

// pack_W: coalesced tiled transpose; block = 16 k-rows x 64 units x 4 gates.
__device__ void pack_W_body(
    float* s_w,
    const float* __restrict__ wxf, const float* __restrict__ wxi,
    const float* __restrict__ wxo, const float* __restrict__ wxg,
    const float* __restrict__ whf, const float* __restrict__ whi,
    const float* __restrict__ who, const float* __restrict__ whg, int blk)
{
    const int tid = threadIdx.x;
    const int kb = blk & 255;                // 256 k16 blocks
    const int ub = blk >> 8;                 // 32 unit-blocks of 64
    const int kbase = kb * 16;
    const int ubase = ub * 64;

    const bool isx = (kbase < UDIM);
    const int klocal = isx ? kbase : (kbase - UDIM);
    const float* Wg[4];
    Wg[0] = isx ? wxf : whf;
    Wg[1] = isx ? wxi : whi;
    Wg[2] = isx ? wxo : who;
    Wg[3] = isx ? wxg : whg;

    // load: per gate, 16 rows x 16 float4, coalesced; s_w row = k_local*4+g
    const int r = tid >> 4, q = tid & 15;
#pragma unroll
    for (int g = 0; g < 4; g++) {
        float4 v = *(const float4*)(Wg[g] + (size_t)(klocal + r) * UDIM +
                                    ubase + q * 4);
        float* d = s_w + (r * 4 + g) * WLD + q * 4;
        d[0] = v.x; d[1] = v.y; d[2] = v.z; d[3] = v.w;
    }
    __syncthreads();

    // emit: 512 uint4 outputs (16 nbp x 32 lanes), 2 per thread
#pragma unroll
    for (int i = 0; i < 2; i++) {
        int o = tid + 256 * i;
        int lane = o & 31;
        int nbpl = o >> 5;                   // 0..15
        int kq = lane & 3, nq = lane >> 2;
        int c0 = nbpl * 16 + nq;             // local col (n) of first frag
        int g = c0 & 3;
        int u0 = c0 >> 2;                    // local unit
        uint4 v;
        v.x = packh2(s_w[((2 * kq) * 4 + g) * WLD + u0],
                     s_w[((2 * kq + 1) * 4 + g) * WLD + u0]);
        v.y = packh2(s_w[((2 * kq + 8) * 4 + g) * WLD + u0],
                     s_w[((2 * kq + 9) * 4 + g) * WLD + u0]);
        v.z = packh2(s_w[((2 * kq) * 4 + g) * WLD + u0 + 2],
                     s_w[((2 * kq + 1) * 4 + g) * WLD + u0 + 2]);
        v.w = packh2(s_w[((2 * kq + 8) * 4 + g) * WLD + u0 + 2],
                     s_w[((2 * kq + 9) * 4 + g) * WLD + u0 + 2]);
        int nbp = ub * 16 + nbpl;
        *(uint4*)(g_Bp + ((size_t)kb * NBPTOT + nbp) * 128 + lane * 4) = v;
    }
}

__global__ void __launch_bounds__(256) pack_AW_kernel(
    const float* __restrict__ x, const float* __restrict__ h,
    const float* __restrict__ wxf, const float* __restrict__ wxi,
    const float* __restrict__ wxo, const float* __restrict__ wxg,
    const float* __restrict__ whf, const float* __restrict__ whi,
    const float* __restrict__ who, const float* __restrict__ whg)
{
    __shared__ float s_w[64 * WLD];
    if (blockIdx.x < NA_BLOCKS)
        pack_A_body(x, h, blockIdx.x);
    else
        pack_W_body(s_w, wxf, wxi, wxo, wxg, whf, whi, who, whg,
                    blockIdx.x - NA_BLOCKS);
}

// ---------------------------------------------------------------- GEMM
__device__ __forceinline__ void load_stage(uint32_t sbase, int slot, int kt,
                                           int tid, int mb0, int nbp0)
{
    uint32_t sa = sbase + slot * STAGE_BYTES;
    uint32_t sb = sa + SA_STAGE;
    const int k16 = kt * 4;
    const uint32_t* a0 = g_Ap + (size_t)k16 * AK16 + mb0 * 128;
    const uint32_t* b0 = g_Bp + (size_t)k16 * BK16 + nbp0 * 128;
#pragma unroll
    for (int j = 0; j < 4; j++) {          // 4 k16 slabs, 4KB each operand
        cp16(sa + j * 4096 + tid * 16,        a0 + (size_t)j * AK16 + tid * 4);
        cp16(sa + j * 4096 + 2048 + tid * 16, a0 + (size_t)j * AK16 + 512 + tid * 4);
        cp16(sb + j * 4096 + tid * 16,        b0 + (size_t)j * BK16 + tid * 4);
        cp16(sb + j * 4096 + 2048 + tid * 16, b0 + (size_t)j * BK16 + 512 + tid * 4);
    }
}

__global__ void __launch_bounds__(NTHREADS, 2) lstm_gemm_kernel(
    const float* __restrict__ cin,
    const float* __restrict__ bfp, const float* __restrict__ bip,
    const float* __restrict__ bop, const float* __restrict__ bgp,
    float* __restrict__ out)
{
    extern __shared__ char smem[];
    const uint32_t sbase = smem_u32(smem);
    const int tid = threadIdx.x;
    const int wid = tid >> 5;
    const int lane = tid & 31;
    const int mt = blockIdx.x & 31;          // m fastest: A stays L2-resident
    const int nt = blockIdx.x >> 5;          // 0..63
    const int mb0 = mt * 8;
    const int nbp0 = nt * 8;

    const int wmi = wid & 1;                 // warp m index (64-row tile)
    const int wni = wid >> 1;                // warp n index (64-col tile)
    const uint32_t a_off = (uint32_t)wmi * 2048 + lane * 16;
    const uint32_t b_off = (uint32_t)wni * 2048 + lane * 16;

    float acc[4][8][4];
#pragma unroll
    for (int mf = 0; mf < 4; mf++)
#pragma unroll
        for (int nf = 0; nf < 8; nf++)
#pragma unroll
            for (int r = 0; r < 4; r++) acc[mf][nf][r] = 0.f;

    // prologue: 2 stages in flight
    load_stage(sbase, 0, 0, tid, mb0, nbp0);
    cp_commit();
    load_stage(sbase, 1, 1, tid, mb0, nbp0);
    cp_commit();
    cp_wait<1>();            // stage 0 complete (self)
    __syncthreads();         // visible to all

    uint32_t a[2][4][4];
    uint32_t b[2][8][2];

    // prime buffer 0 with (kt=0, ks=0) fragments
#pragma unroll
    for (int mf = 0; mf < 4; mf++)
        lds128(a[0][mf], sbase + mf * 512 + a_off);
#pragma unroll
    for (int p = 0; p < 4; p++)
        lds128(&b[0][2 * p][0], sbase + SA_STAGE + p * 512 + b_off);

    const int KT = KTOT / TK;                // 64
    int cs = 0, ls = 2;                      // compute slot, load slot
    for (int kt = 0; kt < KT; kt++) {
        const uint32_t sa = sbase + cs * STAGE_BYTES;
        const uint32_t sb = sa + SA_STAGE;
        const int ns = (cs == 2) ? 0 : cs + 1;
        const uint32_t sa_n = sbase + ns * STAGE_BYTES;
        const uint32_t sb_n = sa_n + SA_STAGE;

        __syncthreads();                     // (A) readers of old slot done
        if (kt + 2 < KT) load_stage(sbase, ls, kt + 2, tid, mb0, nbp0);
        cp_commit();
        cp_wait<1>();                        // stage kt+1 complete (self)
        __syncthreads();                     // (B) stage kt+1 visible to all

#pragma unroll
        for (int ks = 0; ks < 4; ks++) {
            const int cur = ks & 1, nxt = cur ^ 1;
            if (ks < 3) {        // prefetch next ks of this stage
#pragma unroll
                for (int mf = 0; mf < 4; mf++)
                    lds128(a[nxt][mf], sa + (ks + 1) * 4096 + mf * 512 + a_off);
#pragma unroll
                for (int p = 0; p < 4; p++)
                    lds128(&b[nxt][2 * p][0], sb + (ks + 1) * 4096 + p * 512 + b_off);
            } else if (kt + 1 < KT) {   // prefetch ks=0 of NEXT stage
#pragma unroll
                for (int mf = 0; mf < 4; mf++)
                    lds128(a[nxt][mf], sa_n + mf * 512 + a_off);
#pragma unroll
                for (int p = 0; p < 4; p++)
                    lds128(&b[nxt][2 * p][0], sb_n + p * 512 + b_off);
            }
#pragma unroll
            for (int mf = 0; mf < 4; mf++)
#pragma unroll
                for (int nf = 0; nf < 8; nf++)
                    mma16(acc[mf][nf], a[cur][mf], b[cur][nf]);
        }

        cs = ns;
        ls = (ls == 2) ? 0 : ls + 1;
    }

    cp_wait<0>();
    __syncthreads();     // pipeline done; reuse smem for z tile

    // ---- epilogue: single 128x128 z tile through smem ----
    float* s_z = (float*)smem;
    const int gq = lane >> 2, kq = lane & 3;
    const int m0 = mt * TM;
    const size_t HC = (size_t)MTOT * UDIM;

#pragma unroll
    for (int mf = 0; mf < 4; mf++)
#pragma unroll
        for (int nf = 0; nf < 8; nf++) {
            int row = wmi * 64 + mf * 16 + gq;
            int col = wni * 64 + nf * 8 + 2 * kq;
            *(float2*)(s_z + row * ZLD + col) =
                make_float2(acc[mf][nf][0], acc[mf][nf][1]);
            *(float2*)(s_z + (row + 8) * ZLD + col) =
                make_float2(acc[mf][nf][2], acc[mf][nf][3]);
        }
    __syncthreads();

    const int ul = tid & 31;                 // unit lane (32 units per CTA)
    const int rb = tid >> 5;                 // 4 row blocks of 32 rows
    const int u = nt * 32 + ul;
    const float bf = __ldg(bfp + u);
    const float bi = __ldg(bip + u);
    const float bo = __ldg(bop + u);
    const float bg = __ldg(bgp + u);

#pragma unroll 4
    for (int rr = 0; rr < 32; rr++) {
        int row = rb * 32 + rr;
        float4 z = *(const float4*)(s_z + row * ZLD + 4 * ul);
        size_t g = (size_t)(m0 + row) * UDIM + u;
        float zf = z.x + bf, zi = z.y + bi, zo = z.z + bo, zg = z.w + bg;
        float fg = 1.f / (1.f + expf(-zf));
        float ig = 1.f / (1.f + expf(-zi));
        float og = 1.f / (1.f + expf(-zo));
        float gg = tanhf(zg);
        float cn = fg * __ldcs(cin + g) + ig * gg;
        float hn = og * tanhf(cn);
        __stcs(out + g, hn);          // h_new (streaming store)
        __stcs(out + HC + g, cn);     // c_new
    }
}

// ---------------------------------------------------------------- launch
extern "C" void kernel_launch(void* const* d_in, const int* in_sizes, int n_in,
                              void* d_out, int out_size) {
    (void)in_sizes; (void)n_in; (void)out_size;
    const float* x   = (const float*)d_in[0];
    const float* h   = (const float*)d_in[1];
    const float* c   = (const float*)d_in[2];
    const float* Wxf = (const float*)d_in[3];
    const float* Wxi = (const float*)d_in[4];
    const float* Wxo = (const float*)d_in[5];
    const float* Wxg = (const float*)d_in[6];
    const float* bf  = (const float*)d_in[7];
    const float* bi  = (const float*)d_in[8];
    const float* bo  = (const float*)d_in[9];
    const float* bg  = (const float*)d_in[10];
    const float* Whf = (const float*)d_in[11];
    const float* Whi = (const float*)d_in[12];
    const float* Who = (const float*)d_in[13];
    const float* Whg = (const float*)d_in[14];
    float* out = (float*)d_out;

    static int smem_set = 0;
    if (!smem_set) {
        cudaFuncSetAttribute(lstm_gemm_kernel,
                             cudaFuncAttributeMaxDynamicSharedMemorySize,
                             SMEM_BYTES);
        smem_set = 1;
    }

    pack_AW_kernel<<<NA_BLOCKS + NW_BLOCKS, 256>>>(
        x, h, Wxf, Wxi, Wxo, Wxg, Whf, Whi, Who, Whg);
    lstm_gemm_kernel<<<(MTOT / TM) * (NTOT / TN), NTHREADS, SMEM_BYTES>>>(
        c, bf, bi, bo, bg, out);
}

// round 13
// speedup vs baseline: 2.2004x; 1.0143x over previous
#include <cuda_runtime.h>
#include <cuda_fp16.h>
#include <cstdint>

// ============================================================================
// LSTM cell, base sm_103 ISA. fp16 mma.sync m16n8k16, cp.async 4-slot TK=48,
// SINGLE barrier per k-chunk (distance-2 slot reuse makes load-first safe),
// fragment-packed operands, register double-buffered fragments with
// cross-stage prefetch. CTA 128x128, 128 threads, warp tile 64x64, 2 CTAs/SM.
// Fused gate epilogue (fast sigmoid/tanh).
//
// z[4096, 8192] = A[4096, 4096] @ B[4096, 8192]
//   A = [x | h], B[k][4u+g] = W{x,h}{f,i,o,g}[k][u]  (gate-interleaved)
// K padded with 2 zero k16-slices so 86 stages of TK=48 cover K=4096.
// ============================================================================

#define MTOT 4096
#define KTOT 4096
#define NTOT 8192
#define UDIM 2048

#define TM 128
#define TN 128
#define NTHREADS 128

#define MBTOT 256              // MTOT/16
#define NBPTOT 512             // NTOT/16 (n-fragment pairs)
#define K16TOT 256             // KTOT/16
#define K16PAD 258             // +2 zero slices (pad to 86*3)
#define KT 86                  // number of TK=48 stages

#define AK16 (MBTOT * 128)     // uint32 stride per k16 in g_Ap
#define BK16 (NBPTOT * 128)    // uint32 stride per k16 in g_Bp

#define SA_STAGE 12288         // 3 k16 * 8 mb * 512 B
#define SB_STAGE 12288         // 3 k16 * 8 nbp * 512 B
#define STAGE_BYTES (SA_STAGE + SB_STAGE)      // 24576
#define PIPE_BYTES (4 * STAGE_BYTES)           // 98304 (4 slots)
#define ZLD 132                                 // z tile: 128*132*4 = 67584
#define SMEM_BYTES PIPE_BYTES

// Fragment-packed fp16 operands (uint32 = f16x2). Zero-padded k16 256..257
// (device globals are zero-initialized; pack kernels write only 0..255).
static __device__ __align__(16) uint32_t g_Ap[(size_t)K16PAD * AK16];
static __device__ __align__(16) uint32_t g_Bp[(size_t)K16PAD * BK16];

// ---------------------------------------------------------------- helpers
__device__ __forceinline__ uint32_t smem_u32(const void* p) {
    uint32_t a;
    asm("{ .reg .u64 t; cvta.to.shared.u64 t, %1; cvt.u32.u64 %0, t; }"
        : "=r"(a) : "l"(p));
    return a;
}

__device__ __forceinline__ uint32_t packh2(float lo, float hi) {
    __half2 h = __floats2half2_rn(lo, hi);
    return *reinterpret_cast<uint32_t*>(&h);
}

__device__ __forceinline__ void cp16(uint32_t dst, const void* src) {
    asm volatile("cp.async.cg.shared.global [%0], [%1], 16;"
                 :: "r"(dst), "l"(src) : "memory");
}
__device__ __forceinline__ void cp_commit() {
    asm volatile("cp.async.commit_group;" ::: "memory");
}
template <int N>
__device__ __forceinline__ void cp_wait() {
    asm volatile("cp.async.wait_group %0;" :: "n"(N) : "memory");
}

__device__ __forceinline__ void mma16(float* d, const uint32_t* a, const uint32_t* b) {
    asm volatile(
        "mma.sync.aligned.m16n8k16.row.col.f32.f16.f16.f32 "
        "{%0,%1,%2,%3}, {%4,%5,%6,%7}, {%8,%9}, {%0,%1,%2,%3};"
        : "+f"(d[0]), "+f"(d[1]), "+f"(d[2]), "+f"(d[3])
        : "r"(a[0]), "r"(a[1]), "r"(a[2]), "r"(a[3]), "r"(b[0]), "r"(b[1]));
}

__device__ __forceinline__ void lds128(uint32_t* r, uint32_t addr) {
    asm volatile("ld.shared.v4.b32 {%0,%1,%2,%3}, [%4];"
                 : "=r"(r[0]), "=r"(r[1]), "=r"(r[2]), "=r"(r[3]) : "r"(addr));
}

__device__ __forceinline__ float fsig(float z) {        // fast sigmoid
    return __fdividef(1.f, 1.f + __expf(-z));
}
__device__ __forceinline__ float ftanh(float z) {       // tanh = 2*sig(2z)-1
    return __fmaf_rn(2.f, __fdividef(1.f, 1.f + __expf(-2.f * z)), -1.f);
}

// ---------------------------------------------------------------- prepasses
#define NA_BLOCKS 8192
#define NW_BLOCKS 8192
#define WLD 65

__device__ void pack_A_body(const float* __restrict__ x,
                            const float* __restrict__ h, int blk)
{
    uint32_t t = blk * 256 + threadIdx.x;
    int lane = t & 31;
    int mb = (t >> 5) & 255;
    int k16 = t >> 13;                   // 0..255
    int kq = lane & 3, gq = lane >> 2;
    int m = mb * 16 + gq;
    int k = k16 * 16 + 2 * kq;
    const float* src = (k < UDIM) ? (x + k) : (h + (k - UDIM));
    float2 p0 = *(const float2*)(src + (size_t)m * UDIM);
    float2 p1 = *(const float2*)(src + (size_t)(m + 8) * UDIM);
    float2 p2 = *(const float2*)(src + (size_t)m * UDIM + 8);
    float2 p3 = *(const float2*)(src + (size_t)(m + 8) * UDIM + 8);
    uint4 u;
    u.x = packh2(p0.x, p0.y);
    u.y = packh2(p1.x, p1.y);
    u.z = packh2(p2.x, p2.y);
    u.w = packh2(p3.x, p3.y);
    *(uint4*)(g_Ap + (size_t)t * 4) = u;
}

__device__ void pack_W_body(
    float* s_w,
    const float* __restrict__ wxf, const float* __restrict__ wxi,
    const float* __restrict__ wxo, const float* __restrict__ wxg,
    const float* __restrict__ whf, const float* __restrict__ whi,
    const float* __restrict__ who, const float* __restrict__ whg, int blk)
{
    const int tid = threadIdx.x;
    const int kb = blk & 255;                // 256 k16 blocks
    const int ub = blk >> 8;                 // 32 unit-blocks of 64
    const int kbase = kb * 16;
    const int ubase = ub * 64;

    const bool isx = (kbase < UDIM);
    const int klocal = isx ? kbase : (kbase - UDIM);
    const float* Wg[4];
    Wg[0] = isx ? wxf : whf;
    Wg[1] = isx ? wxi : whi;
    Wg[2] = isx ? wxo : who;
    Wg[3] = isx ? wxg : whg;

    const int r = tid >> 4, q = tid & 15;
#pragma unroll
    for (int g = 0; g < 4; g++) {
        float4 v = *(const float4*)(Wg[g] + (size_t)(klocal + r) * UDIM +
                                    ubase + q * 4);
        float* d = s_w + (r * 4 + g) * WLD + q * 4;
        d[0] = v.x; d[1] = v.y; d[2] = v.z; d[3] = v.w;
    }
    __syncthreads();

#pragma unroll
    for (int i = 0; i < 2; i++) {
        int o = tid + 256 * i;
        int lane = o & 31;
        int nbpl = o >> 5;                   // 0..15
        int kq = lane & 3, nq = lane >> 2;
        int c0 = nbpl * 16 + nq;
        int g = c0 & 3;
        int u0 = c0 >> 2;
        uint4 v;
        v.x = packh2(s_w[((2 * kq) * 4 + g) * WLD + u0],
                     s_w[((2 * kq + 1) * 4 + g) * WLD + u0]);
        v.y = packh2(s_w[((2 * kq + 8) * 4 + g) * WLD + u0],
                     s_w[((2 * kq + 9) * 4 + g) * WLD + u0]);
        v.z = packh2(s_w[((2 * kq) * 4 + g) * WLD + u0 + 2],
                     s_w[((2 * kq + 1) * 4 + g) * WLD + u0 + 2]);
        v.w = packh2(s_w[((2 * kq + 8) * 4 + g) * WLD + u0 + 2],
                     s_w[((2 * kq + 9) * 4 + g) * WLD + u0 + 2]);
        int nbp = ub * 16 + nbpl;
        *(uint4*)(g_Bp + ((size_t)kb * NBPTOT + nbp) * 128 + lane * 4) = v;
    }
}

__global__ void __launch_bounds__(256) pack_AW_kernel(
    const float* __restrict__ x, const float* __restrict__ h,
    const float* __restrict__ wxf, const float* __restrict__ wxi,
    const float* __restrict__ wxo, const float* __restrict__ wxg,
    const float* __restrict__ whf, const float* __restrict__ whi,
    const float* __restrict__ who, const float* __restrict__ whg)
{
    __shared__ float s_w[64 * WLD];
    if (blockIdx.x < NA_BLOCKS)
        pack_A_body(x, h, blockIdx.x);
    else
        pack_W_body(s_w, wxf, wxi, wxo, wxg, whf, whi, who, whg,
                    blockIdx.x - NA_BLOCKS);
}

// ---------------------------------------------------------------- GEMM
__device__ __forceinline__ void load_stage(uint32_t sbase, int slot, int st,
                                           int tid, int mb0, int nbp0)
{
    uint32_t sa = sbase + slot * STAGE_BYTES;
    uint32_t sb = sa + SA_STAGE;
    const int k16 = st * 3;
    const uint32_t* a0 = g_Ap + (size_t)k16 * AK16 + mb0 * 128;
    const uint32_t* b0 = g_Bp + (size_t)k16 * BK16 + nbp0 * 128;
#pragma unroll
    for (int j = 0; j < 3; j++) {          // 3 k16 slabs, 4KB each operand
        cp16(sa + j * 4096 + tid * 16,        a0 + (size_t)j * AK16 + tid * 4);
        cp16(sa + j * 4096 + 2048 + tid * 16, a0 + (size_t)j * AK16 + 512 + tid * 4);
        cp16(sb + j * 4096 + tid * 16,        b0 + (size_t)j * BK16 + tid * 4);
        cp16(sb + j * 4096 + 2048 + tid * 16, b0 + (size_t)j * BK16 + 512 + tid * 4);
    }
}

// One TK=48 chunk. PAR = (3*kt)&1 resolves the register-ring parity
// (3 ks per chunk flips parity each chunk; kt loop is unrolled by 2).
template <int PAR>
__device__ __forceinline__ void kt_body(
    int kt, uint32_t sbase, int tid, int mb0, int nbp0,
    uint32_t a_off, uint32_t b_off,
    uint32_t (&a)[2][4][4], uint32_t (&b)[2][8][2],
    float (&acc)[4][8][4])
{
    // Single-barrier ordering (safe: written slot (kt+2)&3 was last read at
    // kt-2, and every thread passed the kt-1 barrier before this load):
    if (kt + 2 < KT) load_stage(sbase, (kt + 2) & 3, kt + 2, tid, mb0, nbp0);
    cp_commit();
    cp_wait<1>();        // stage kt+1 complete (self); kt+2 stays in flight
    __syncthreads();     // publish kt+1 to all; lockstep for slot safety

    const uint32_t sa = sbase + (kt & 3) * STAGE_BYTES;
    const uint32_t sb = sa + SA_STAGE;
    const uint32_t sa_n = sbase + ((kt + 1) & 3) * STAGE_BYTES;
    const uint32_t sb_n = sa_n + SA_STAGE;

#pragma unroll
    for (int ks = 0; ks < 3; ks++) {
        const int cur = (ks + PAR) & 1, nxt = cur ^ 1;
        if (ks < 2) {        // prefetch next slab of this stage
#pragma unroll
            for (int mf = 0; mf < 4; mf++)
                lds128(a[nxt][mf], sa + (ks + 1) * 4096 + mf * 512 + a_off);
#pragma unroll
            for (int p = 0; p < 4; p++)
                lds128(&b[nxt][2 * p][0], sb + (ks + 1) * 4096 + p * 512 + b_off);
        } else if (kt + 1 < KT) {   // prefetch slab 0 of NEXT stage
#pragma unroll
            for (int mf = 0; mf < 4; mf++)
                lds128(a[nxt][mf], sa_n + mf * 512 + a_off);
#pragma unroll
            for (int p = 0; p < 4; p++)
                lds128(&b[nxt][2 * p][0], sb_n + p * 512 + b_off);
        }
#pragma unroll
        for (int mf = 0; mf < 4; mf++)
#pragma unroll
            for (int nf = 0; nf < 8; nf++)
                mma16(acc[mf][nf], a[cur][mf], b[cur][nf]);
    }
}

__global__ void __launch_bounds__(NTHREADS, 2) lstm_gemm_kernel(
    const float* __restrict__ cin,
    const float* __restrict__ bfp, const float* __restrict__ bip,
    const float* __restrict__ bop, const float* __restrict__ bgp,
    float* __restrict__ out)
{
    extern __shared__ char smem[];
    const uint32_t sbase = smem_u32(smem);
    const int tid = threadIdx.x;
    const int wid = tid >> 5;
    const int lane = tid & 31;
    const int mt = blockIdx.x & 31;          // m fastest: A stays L2-resident
    const int nt = blockIdx.x >> 5;          // 0..63
    const int mb0 = mt * 8;
    const int nbp0 = nt * 8;

    const int wmi = wid & 1;                 // warp m index (64-row tile)
    const int wni = wid >> 1;                // warp n index (64-col tile)
    const uint32_t a_off = (uint32_t)wmi * 2048 + lane * 16;
    const uint32_t b_off = (uint32_t)wni * 2048 + lane * 16;

    float acc[4][8][4];
#pragma unroll
    for (int mf = 0; mf < 4; mf++)
#pragma unroll
        for (int nf = 0; nf < 8; nf++)
#pragma unroll
            for (int r = 0; r < 4; r++) acc[mf][nf][r] = 0.f;

    // prologue: stages 0 and 1 in flight
    load_stage(sbase, 0, 0, tid, mb0, nbp0);
    cp_commit();
    load_stage(sbase, 1, 1, tid, mb0, nbp0);
    cp_commit();
    cp_wait<1>();            // stage 0 complete (self)
    __syncthreads();         // visible to all

    uint32_t a[2][4][4];
    uint32_t b[2][8][2];

    // prime buffer 0 with (stage 0, ks=0) fragments
#pragma unroll
    for (int mf = 0; mf < 4; mf++)
        lds128(a[0][mf], sbase + mf * 512 + a_off);
#pragma unroll
    for (int p = 0; p < 4; p++)
        lds128(&b[0][2 * p][0], sbase + SA_STAGE + p * 512 + b_off);

    for (int kt = 0; kt < KT; kt += 2) {     // KT=86 (even)
        kt_body<0>(kt,     sbase, tid, mb0, nbp0, a_off, b_off, a, b, acc);
        kt_body<1>(kt + 1, sbase, tid, mb0, nbp0, a_off, b_off, a, b, acc);
    }

    cp_wait<0>();
    __syncthreads();     // pipeline done; reuse smem for z tile

    // ---- epilogue: single 128x128 z tile through smem ----
    float* s_z = (float*)smem;
    const int gq = lane >> 2, kq = lane & 3;
    const int m0 = mt * TM;
    const size_t HC = (size_t)MTOT * UDIM;

#pragma unroll
    for (int mf = 0; mf < 4; mf++)
#pragma unroll
        for (int nf = 0; nf < 8; nf++) {
            int row = wmi * 64 + mf * 16 + gq;
            int col = wni * 64 + nf * 8 + 2 * kq;
            *(float2*)(s_z + row * ZLD + col) =
                make_float2(acc[mf][nf][0], acc[mf][nf][1]);
            *(float2*)(s_z + (row + 8) * ZLD + col) =
                make_float2(acc[mf][nf][2], acc[mf][nf][3]);
        }
    __syncthreads();

    const int ul = tid & 31;                 // unit lane (32 units per CTA)
    const int rb = tid >> 5;                 // 4 row blocks of 32 rows
    const int u = nt * 32 + ul;
    const float bf = __ldg(bfp + u);
    const float bi = __ldg(bip + u);
    const float bo = __ldg(bop + u);
    const float bg = __ldg(bgp + u);

#pragma unroll 4
    for (int rr = 0; rr < 32; rr++) {
        int row = rb * 32 + rr;
        float4 z = *(const float4*)(s_z + row * ZLD + 4 * ul);
        size_t g = (size_t)(m0 + row) * UDIM + u;
        float fg = fsig(z.x + bf);
        float ig = fsig(z.y + bi);
        float og = fsig(z.z + bo);
        float gg = ftanh(z.w + bg);
        float cn = fg * __ldcs(cin + g) + ig * gg;
        float hn = og * ftanh(cn);
        __stcs(out + g, hn);          // h_new (streaming store)
        __stcs(out + HC + g, cn);     // c_new
    }
}

// ---------------------------------------------------------------- launch
extern "C" void kernel_launch(void* const* d_in, const int* in_sizes, int n_in,
                              void* d_out, int out_size) {
    (void)in_sizes; (void)n_in; (void)out_size;
    const float* x   = (const float*)d_in[0];
    const float* h   = (const float*)d_in[1];
    const float* c   = (const float*)d_in[2];
    const float* Wxf = (const float*)d_in[3];
    const float* Wxi = (const float*)d_in[4];
    const float* Wxo = (const float*)d_in[5];
    const float* Wxg = (const float*)d_in[6];
    const float* bf  = (const float*)d_in[7];
    const float* bi  = (const float*)d_in[8];
    const float* bo  = (const float*)d_in[9];
    const float* bg  = (const float*)d_in[10];
    const float* Whf = (const float*)d_in[11];
    const float* Whi = (const float*)d_in[12];
    const float* Who = (const float*)d_in[13];
    const float* Whg = (const float*)d_in[14];
    float* out = (float*)d_out;

    static int smem_set = 0;
    if (!smem_set) {
        cudaFuncSetAttribute(lstm_gemm_kernel,
                             cudaFuncAttributeMaxDynamicSharedMemorySize,
                             SMEM_BYTES);
        smem_set = 1;
    }

    pack_AW_kernel<<<NA_BLOCKS + NW_BLOCKS, 256>>>(
        x, h, Wxf, Wxi, Wxo, Wxg, Whf, Whi, Who, Whg);
    lstm_gemm_kernel<<<(MTOT / TM) * (NTOT / TN), NTHREADS, SMEM_BYTES>>>(
        c, bf, bi, bo, bg, out);
}